// round 1
// baseline (speedup 1.0000x reference)
#include <cuda_runtime.h>
#include <cstddef>

#define B_DIM 4096
#define K_DIM 64
#define D_DIM 512
#define N_AGENTS 64
#define NEG_INF -1e9f
#define THREADS 512

__global__ __launch_bounds__(THREADS, 1)
void block_diag_agg_kernel(const float* __restrict__ h,
                           const float* __restrict__ keys,
                           const int* __restrict__ sigma,
                           float* __restrict__ out) {
    extern __shared__ float sh[];            // 64 * 512 floats = 128 KB (h tile)
    __shared__ float s_alpha[K_DIM];

    const int b    = blockIdx.x;
    const int tid  = threadIdx.x;
    const int warp = tid >> 5;
    const int lane = tid & 31;

    const float* hb = h + (size_t)b * (K_DIM * D_DIM);
    const int*   sb = sigma + (size_t)b * K_DIM;

    // ---- Phase 1: per-slot dot products; stage h[b] into smem on the way ----
    // 16 warps, each handles 4 consecutive k slots.
    float logit_loc[4];
    int   k_loc[4];
    #pragma unroll
    for (int i = 0; i < 4; i++) {
        const int k = warp * 4 + i;
        k_loc[i] = k;
        const int sid   = sb[k];
        const bool valid = (sid < N_AGENTS);
        const float4* hrow = (const float4*)(hb + (size_t)k * D_DIM);
        const float4* krow = (const float4*)(keys + (size_t)(valid ? sid : 0) * D_DIM);

        float acc = 0.0f;
        #pragma unroll
        for (int j = 0; j < 4; j++) {
            const int idx = lane + 32 * j;           // 0..127 float4 per row
            float4 hv = hrow[idx];
            float4 kv = krow[idx];
            acc = fmaf(hv.x, kv.x, acc);
            acc = fmaf(hv.y, kv.y, acc);
            acc = fmaf(hv.z, kv.z, acc);
            acc = fmaf(hv.w, kv.w, acc);
            ((float4*)sh)[k * (D_DIM / 4) + idx] = hv;   // stage to smem
        }
        // warp reduction of the dot product
        #pragma unroll
        for (int off = 16; off > 0; off >>= 1)
            acc += __shfl_xor_sync(0xFFFFFFFFu, acc, off);
        logit_loc[i] = valid ? acc : NEG_INF;
    }

    // lane 0 of each warp publishes its 4 logits
    __shared__ float s_logits[K_DIM];
    if (lane == 0) {
        #pragma unroll
        for (int i = 0; i < 4; i++) s_logits[k_loc[i]] = logit_loc[i];
    }
    __syncthreads();

    // ---- Phase 2: softmax over K=64 (warp 0 only, 2 logits per lane) ----
    if (warp == 0) {
        float l0 = s_logits[lane];
        float l1 = s_logits[lane + 32];
        float m = fmaxf(l0, l1);
        #pragma unroll
        for (int off = 16; off > 0; off >>= 1)
            m = fmaxf(m, __shfl_xor_sync(0xFFFFFFFFu, m, off));
        float e0 = expf(l0 - m);
        float e1 = expf(l1 - m);
        float s = e0 + e1;
        #pragma unroll
        for (int off = 16; off > 0; off >>= 1)
            s += __shfl_xor_sync(0xFFFFFFFFu, s, off);
        float inv = 1.0f / s;
        s_alpha[lane]      = e0 * inv;
        s_alpha[lane + 32] = e1 * inv;
    }
    __syncthreads();

    // ---- Phase 3: weighted pooling from smem; thread tid owns dim d = tid ----
    float acc = 0.0f;
    #pragma unroll 16
    for (int k = 0; k < K_DIM; k++) {
        acc = fmaf(s_alpha[k], sh[k * D_DIM + tid], acc);
    }
    out[(size_t)b * D_DIM + tid] = acc;
}

extern "C" void kernel_launch(void* const* d_in, const int* in_sizes, int n_in,
                              void* d_out, int out_size) {
    const float* h     = (const float*)d_in[0];
    const float* keys  = (const float*)d_in[1];
    const int*   sigma = (const int*)d_in[2];
    float*       out   = (float*)d_out;

    const int smem_bytes = K_DIM * D_DIM * (int)sizeof(float);  // 128 KB
    cudaFuncSetAttribute(block_diag_agg_kernel,
                         cudaFuncAttributeMaxDynamicSharedMemorySize, smem_bytes);

    block_diag_agg_kernel<<<B_DIM, THREADS, smem_bytes>>>(h, keys, sigma, out);
}